// round 6
// baseline (speedup 1.0000x reference)
#include <cuda_runtime.h>
#include <math.h>

// CRU: B=2048, T=512, D=64, H=512, NT=8, IN=128
// Strategy: 512 graph-captured step launches. Each step launch:
//   grid (32 nh, 4 mb) = 128 CTAs, 512 threads.
//   CTA owns HJ=16 hidden units (48 gate rows r,z,n) x MB=512 batch rows.
//   W slice (48 x 640) resident in smem; A = [h(512) | inp(128)] staged in
//   K-chunks of 32 through smem. h stored transposed [H][B] in ping-pong
//   device globals; decay applied at WRITE time (h_store = h_new * decay_{t+1}).

#define HB (512 * 2048)

__device__ float g_h0[HB];
__device__ float g_h1[HB];
__device__ float g_dt[512 * 2048];   // [t][b] : dt_t = ts[t]-ts[t-1], dt_0 = 0

#define SMW_FLOATS (640 * 48)
#define SMA_STRIDE 516               // 512 + 4 pad (keeps 16B row alignment)
#define SMA_FLOATS (32 * SMA_STRIDE)
#define SMEM_BYTES ((SMW_FLOATS + SMA_FLOATS) * 4)   // 188,928 B

__device__ __forceinline__ float sigmoidf_(float x) {
    return 1.0f / (1.0f + __expf(-x));
}

// One K-slice of the register-blocked GEMM: 8 batch rows x 2 hidden units x 3 gates.
__device__ __forceinline__ void mma_tile(const float* __restrict__ ar,
                                         const float* __restrict__ wr,
                                         float* accR, float* accZ, float* accN)
{
    float4 a0 = *reinterpret_cast<const float4*>(ar);
    float4 a1 = *reinterpret_cast<const float4*>(ar + 4);
    float2 w01 = *reinterpret_cast<const float2*>(wr);
    float2 w23 = *reinterpret_cast<const float2*>(wr + 2);
    float2 w45 = *reinterpret_cast<const float2*>(wr + 4);
    float a[8] = {a0.x, a0.y, a0.z, a0.w, a1.x, a1.y, a1.z, a1.w};
    float wr0 = w01.x, wz0 = w01.y, wn0 = w23.x;
    float wr1 = w23.y, wz1 = w45.x, wn1 = w45.y;
#pragma unroll
    for (int b = 0; b < 8; b++) {
        accR[b * 2]     = fmaf(a[b], wr0, accR[b * 2]);
        accZ[b * 2]     = fmaf(a[b], wz0, accZ[b * 2]);
        accN[b * 2]     = fmaf(a[b], wn0, accN[b * 2]);
        accR[b * 2 + 1] = fmaf(a[b], wr1, accR[b * 2 + 1]);
        accZ[b * 2 + 1] = fmaf(a[b], wz1, accZ[b * 2 + 1]);
        accN[b * 2 + 1] = fmaf(a[b], wn1, accN[b * 2 + 1]);
    }
}

__global__ void cru_dt_kernel(const float* __restrict__ ts)
{
    int t = blockIdx.x;
    for (int b = threadIdx.x; b < 2048; b += 256) {
        float d = 0.0f;
        if (t > 0)
            d = ts[(size_t)b * 512 + t] - ts[(size_t)b * 512 + t - 1];
        g_dt[t * 2048 + b] = d;
    }
}

__global__ void __launch_bounds__(512, 1) cru_step_kernel(
    const float* __restrict__ vals, const float* __restrict__ maskp,
    const float* __restrict__ W_ih, const float* __restrict__ W_hh,
    const float* __restrict__ b_ih, const float* __restrict__ b_hh,
    const float* __restrict__ W_dec, const float* __restrict__ b_dec,
    int t)
{
    extern __shared__ float sm[];
    float* smW = sm;                 // [640][48] k-major, col = jl*3 + gate
    float* smA = sm + SMW_FLOATS;    // [32][516]

    const int tid = threadIdx.x;
    const int j0 = blockIdx.x * 16;      // hidden-tile base
    const int B0 = blockIdx.y * 512;     // batch-tile base
    const int tx = tid & 63;             // 64 batch groups of 8
    const int ty = tid >> 6;             // 8 col groups of 2 hidden units
    const int wlane = tid & 31, warp = tid >> 5;

    const float* h_prev = (t & 1) ? g_h1 : g_h0;
    float*       h_next = (t & 1) ? g_h0 : g_h1;

    // Fill resident W slice: k<512 -> W_hh row (g*512 + j), k>=512 -> W_ih.
    for (int i = tid; i < 48 * 640; i += 512) {
        int col = i / 640;
        int k   = i - col * 640;
        int jl  = col / 3;
        int g   = col - jl * 3;
        int row = g * 512 + j0 + jl;
        float w = (k < 512) ? W_hh[(size_t)row * 512 + k]
                            : W_ih[(size_t)row * 128 + (k - 512)];
        smW[k * 48 + col] = w;
    }

    float accR[16], accZ[16], accNI[16], accNH[16];
#pragma unroll
    for (int i = 0; i < 16; i++) { accR[i] = 0.f; accZ[i] = 0.f; accNI[i] = 0.f; accNH[i] = 0.f; }

    // ---- Phase H: gates += h_decayed @ W_hh^T (h stored already decayed) ----
    if (t > 0) {
        for (int c = 0; c < 16; ++c) {
            __syncthreads();
            const int kbase = c * 32;
            {   // warp stages rows kbase + 2*warp, +1  (coalesced over b)
                const float* src = h_prev + (size_t)(kbase + warp * 2) * 2048 + B0 + wlane;
                float* dst = smA + (warp * 2) * SMA_STRIDE + wlane;
#pragma unroll
                for (int q = 0; q < 16; ++q) {
                    dst[q * 32]              = src[q * 32];
                    dst[SMA_STRIDE + q * 32] = src[2048 + q * 32];
                }
            }
            __syncthreads();
#pragma unroll 2
            for (int kk = 0; kk < 32; ++kk)
                mma_tile(smA + kk * SMA_STRIDE + tx * 8,
                         smW + (kbase + kk) * 48 + ty * 6, accR, accZ, accNH);
        }
    }

    // ---- Phase I: gates += [values|mask] @ W_ih^T ----
    for (int c = 0; c < 4; ++c) {
        __syncthreads();
        const int kc = c * 32;
        {   // lanes cover k (coalesced global reads), transpose into smA[k][b]
            const int k = kc + wlane;
            const float* base = (k < 64) ? (vals + (size_t)t * 64 + k)
                                         : (maskp + (size_t)t * 64 + (k - 64));
#pragma unroll
            for (int q = 0; q < 32; ++q) {
                int b = q * 16 + warp;
                smA[wlane * SMA_STRIDE + b] = base[(size_t)(B0 + b) * 32768];
            }
        }
        __syncthreads();
#pragma unroll 2
        for (int kk = 0; kk < 32; ++kk)
            mma_tile(smA + kk * SMA_STRIDE + tx * 8,
                     smW + (512 + kc + kk) * 48 + ty * 6, accR, accZ, accNI);
    }

    // ---- Gating + write h_next (decay of step t+1 pre-applied) ----
    const int jA = j0 + ty * 2;
    float biR[2], biZ[2], biN[2], bhR[2], bhZ[2], bhN[2], wd[2], bd[2];
#pragma unroll
    for (int jj = 0; jj < 2; jj++) {
        int j = jA + jj;
        biR[jj] = b_ih[j];        biZ[jj] = b_ih[512 + j];  biN[jj] = b_ih[1024 + j];
        bhR[jj] = b_hh[j];        bhZ[jj] = b_hh[512 + j];  bhN[jj] = b_hh[1024 + j];
        wd[jj]  = W_dec[j];       bd[jj]  = b_dec[j];
    }

    float hu[2][8];
    if (t > 0) {
#pragma unroll
        for (int jj = 0; jj < 2; jj++) {
            const float4* p = reinterpret_cast<const float4*>(
                h_prev + (size_t)(jA + jj) * 2048 + B0 + tx * 8);
            float4 v0 = p[0], v1 = p[1];
            hu[jj][0] = v0.x; hu[jj][1] = v0.y; hu[jj][2] = v0.z; hu[jj][3] = v0.w;
            hu[jj][4] = v1.x; hu[jj][5] = v1.y; hu[jj][6] = v1.z; hu[jj][7] = v1.w;
        }
    } else {
#pragma unroll
        for (int jj = 0; jj < 2; jj++)
#pragma unroll
            for (int bb = 0; bb < 8; bb++) hu[jj][bb] = 0.f;
    }

    float dtn[8];
    if (t < 511) {
        const float4* p = reinterpret_cast<const float4*>(
            g_dt + (size_t)(t + 1) * 2048 + B0 + tx * 8);
        float4 v0 = p[0], v1 = p[1];
        dtn[0] = v0.x; dtn[1] = v0.y; dtn[2] = v0.z; dtn[3] = v0.w;
        dtn[4] = v1.x; dtn[5] = v1.y; dtn[6] = v1.z; dtn[7] = v1.w;
    }

#pragma unroll
    for (int jj = 0; jj < 2; jj++) {
        float ho[8];
#pragma unroll
        for (int bb = 0; bb < 8; bb++) {
            int idx = bb * 2 + jj;
            float r = sigmoidf_(accR[idx] + biR[jj] + bhR[jj]);
            float z = sigmoidf_(accZ[idx] + biZ[jj] + bhZ[jj]);
            float n = tanhf(accNI[idx] + biN[jj] + r * (accNH[idx] + bhN[jj]));
            float h = (1.0f - z) * n + z * hu[jj][bb];
            if (t < 511)  // exp(-softplus(x)) == sigmoid(-x)
                h *= sigmoidf_(-(dtn[bb] * wd[jj] + bd[jj]));
            ho[bb] = h;
        }
        float4* q = reinterpret_cast<float4*>(
            h_next + (size_t)(jA + jj) * 2048 + B0 + tx * 8);
        q[0] = make_float4(ho[0], ho[1], ho[2], ho[3]);
        q[1] = make_float4(ho[4], ho[5], ho[6], ho[7]);
    }
}

__global__ void cru_head_kernel(const float* __restrict__ W_head,
                                const float* __restrict__ b_head,
                                float* __restrict__ out)
{
    __shared__ float sW[8 * 512];
    int tid = threadIdx.x;
    for (int i = tid; i < 4096; i += 128) sW[i] = W_head[i];
    __syncthreads();
    int b = blockIdx.x * 128 + tid;
    float acc[8];
#pragma unroll
    for (int n = 0; n < 8; n++) acc[n] = 0.f;
    for (int j = 0; j < 512; ++j) {
        float hv = g_h0[(size_t)j * 2048 + b];   // final h lives in g_h0 (t=511 writes buf 0)
#pragma unroll
        for (int n = 0; n < 8; n++) acc[n] = fmaf(hv, sW[n * 512 + j], acc[n]);
    }
#pragma unroll
    for (int n = 0; n < 8; n++) out[b * 8 + n] = acc[n] + b_head[n];
}

extern "C" void kernel_launch(void* const* d_in, const int* in_sizes, int n_in,
                              void* d_out, int out_size)
{
    const float* vals   = (const float*)d_in[0];
    const float* maskp  = (const float*)d_in[1];
    const float* ts     = (const float*)d_in[2];
    const float* W_ih   = (const float*)d_in[3];
    const float* W_hh   = (const float*)d_in[4];
    const float* b_ih   = (const float*)d_in[5];
    const float* b_hh   = (const float*)d_in[6];
    const float* W_dec  = (const float*)d_in[7];
    const float* b_dec  = (const float*)d_in[8];
    const float* W_head = (const float*)d_in[9];
    const float* b_head = (const float*)d_in[10];
    float* out = (float*)d_out;

    cudaFuncSetAttribute(cru_step_kernel,
                         cudaFuncAttributeMaxDynamicSharedMemorySize, SMEM_BYTES);

    cru_dt_kernel<<<512, 256>>>(ts);

    dim3 grid(32, 4);
    for (int t = 0; t < 512; ++t)
        cru_step_kernel<<<grid, 512, SMEM_BYTES>>>(
            vals, maskp, W_ih, W_hh, b_ih, b_hh, W_dec, b_dec, t);

    cru_head_kernel<<<16, 128>>>(W_head, b_head, out);
}

// round 11
// speedup vs baseline: 3.0206x; 3.0206x over previous
#include <cuda_runtime.h>
#include <cstdint>
#include <math.h>

// CRU: B=2048, T=512, D=64, H=512, NT=8
// Recurrence on tensor pipe via Ampere-baseline mma.sync.m16n8k8.tf32
// (valid on sm_103 AND sm_103a -- no arch-specific instructions anywhere).
//
// Per step t (one launch, grid (16 m, 8 nt), 256 threads):
//   A (ping-pong) = [ h_tf32 (512) | inp_t (128) ]  row-major [2048][640]
//   gW [1536][640]: per nt-tile gate-blocked: rows nt*192 + g*64 + jl,
//                   k<512 -> W_hh[g*512+j][k], k>=512 -> W_ih[g*512+j][k-512]
//   gWn[512][128] : W_ih n-gate rows only (side GEMM to split gi_n / gh_n)
//   gF (ping-pong) = full-fp32 h for the z*h_prev blend + final head GEMM.
//   Epilogue: fused gates; h_next stored with decay_{t+1} pre-applied.

__device__ float g_A0[2048 * 640];
__device__ float g_A1[2048 * 640];
__device__ float g_F0[2048 * 512];
__device__ float g_F1[2048 * 512];
__device__ float g_W [1536 * 640];
__device__ float g_Wn[ 512 * 128];
__device__ float g_dt[ 512 * 2048];

// smem layout (floats), strides padded to 36 for conflict-free frag loads
#define S_A(d)   ((d) * 4608)                 // [128][36] x2
#define S_W(d)   (9216 + (d) * 6912)          // [192][36] x2
#define S_WN(d)  (23040 + (d) * 2304)         // [64][36]  x2
#define SMEM_FLOATS 27648
#define SMEM_BYTES  (SMEM_FLOATS * 4)         // 110592

__device__ __forceinline__ uint32_t s2u(const void* p) {
    uint32_t a;
    asm("{ .reg .u64 t; cvta.to.shared.u64 t, %1; cvt.u32.u64 %0, t; }" : "=r"(a) : "l"(p));
    return a;
}
__device__ __forceinline__ void cpa16(uint32_t dst, const void* src) {
    asm volatile("cp.async.cg.shared.global [%0], [%1], 16;" :: "r"(dst), "l"(src));
}
#define CPA_COMMIT() asm volatile("cp.async.commit_group;" ::: "memory")
#define CPA_WAIT1()  asm volatile("cp.async.wait_group 1;" ::: "memory")
#define CPA_WAIT0()  asm volatile("cp.async.wait_group 0;" ::: "memory")

__device__ __forceinline__ void mma8(float* c, uint32_t a0, uint32_t a1,
                                     uint32_t a2, uint32_t a3,
                                     uint32_t b0, uint32_t b1) {
    asm volatile("mma.sync.aligned.m16n8k8.row.col.f32.tf32.tf32.f32 "
        "{%0,%1,%2,%3}, {%4,%5,%6,%7}, {%8,%9}, {%0,%1,%2,%3};"
        : "+f"(c[0]), "+f"(c[1]), "+f"(c[2]), "+f"(c[3])
        : "r"(a0), "r"(a1), "r"(a2), "r"(a3), "r"(b0), "r"(b1));
}

__device__ __forceinline__ float tf32r(float x) {
    uint32_t u; asm("cvt.rna.tf32.f32 %0, %1;" : "=r"(u) : "f"(x));
    return __uint_as_float(u);
}
__device__ __forceinline__ float sigmoidf_(float x) { return 1.0f / (1.0f + __expf(-x)); }
__device__ __forceinline__ float tanhfast(float x) {
    float y; asm("tanh.approx.f32 %0, %1;" : "=f"(y) : "f"(x)); return y;
}

// ---------------- prep kernels ----------------
__global__ void prep_w_kernel(const float* __restrict__ W_ih, const float* __restrict__ W_hh) {
    int idx = blockIdx.x * 256 + threadIdx.x;          // 1536*640
    if (idx >= 1536 * 640) return;
    int r = idx / 640, k = idx - r * 640;
    int nt = r / 192, rem = r - nt * 192;
    int g = rem / 64, jl = rem - g * 64;
    int row = g * 512 + nt * 64 + jl;
    float w = (k < 512) ? W_hh[(size_t)row * 512 + k] : W_ih[(size_t)row * 128 + (k - 512)];
    g_W[idx] = tf32r(w);
}
__global__ void prep_wn_kernel(const float* __restrict__ W_ih) {
    int idx = blockIdx.x * 256 + threadIdx.x;          // 512*128
    int j = idx >> 7, k = idx & 127;
    g_Wn[idx] = tf32r(W_ih[(size_t)(1024 + j) * 128 + k]);
}
__global__ void prep_dt_kernel(const float* __restrict__ ts) {
    int t = blockIdx.x;
    for (int b = threadIdx.x; b < 2048; b += 256) {
        float d = 0.0f;
        if (t > 0) d = ts[(size_t)b * 512 + t] - ts[(size_t)b * 512 + t - 1];
        g_dt[t * 2048 + b] = d;
    }
}
__global__ void prep_a0_kernel(const float* __restrict__ vals, const float* __restrict__ maskp) {
    int b = blockIdx.x;
    for (int i = threadIdx.x; i < 640; i += 256) {
        float v = 0.0f;
        if (i >= 512 && i < 576)      v = tf32r(vals [(size_t)b * 32768 + (i - 512)]);
        else if (i >= 576)            v = tf32r(maskp[(size_t)b * 32768 + (i - 576)]);
        g_A0[(size_t)b * 640 + i] = v;
    }
    for (int i = threadIdx.x; i < 512; i += 256)
        g_F0[(size_t)b * 512 + i] = 0.0f;
}

// ---------------- step kernel ----------------
__device__ __forceinline__ void load_chunk(uint32_t sbF, int d,
    const float* __restrict__ Acur, int m_blk, int nt, int kbase, int tid)
{
#pragma unroll
    for (int i = 0; i < 4; i++) {                       // A: 128 x 32
        int op = tid + i * 256;
        int m = op >> 3, seg = op & 7;
        uint32_t dst = sbF + (uint32_t)(S_A(d) + m * 36 + seg * 4) * 4u;
        cpa16(dst, Acur + (size_t)(m_blk * 128 + m) * 640 + kbase + seg * 4);
    }
#pragma unroll
    for (int i = 0; i < 6; i++) {                       // W: 192 x 32
        int op = tid + i * 256;
        int n = op >> 3, seg = op & 7;
        uint32_t dst = sbF + (uint32_t)(S_W(d) + n * 36 + seg * 4) * 4u;
        cpa16(dst, g_W + (size_t)(nt * 192 + n) * 640 + kbase + seg * 4);
    }
    if (kbase >= 512) {
#pragma unroll
        for (int i = 0; i < 2; i++) {                   // Wn: 64 x 32
            int op = tid + i * 256;
            int n = op >> 3, seg = op & 7;
            uint32_t dst = sbF + (uint32_t)(S_WN(d) + n * 36 + seg * 4) * 4u;
            cpa16(dst, g_Wn + (size_t)(nt * 64 + n) * 128 + (kbase - 512) + seg * 4);
        }
    }
    CPA_COMMIT();
}

__global__ void __launch_bounds__(256, 1) cru_step_kernel(
    const float* __restrict__ vals, const float* __restrict__ maskp,
    const float* __restrict__ b_ih, const float* __restrict__ b_hh,
    const float* __restrict__ Wd,  const float* __restrict__ bdp,
    const float* __restrict__ Acur, float* __restrict__ Anext,
    const float* __restrict__ Fcur, float* __restrict__ Fnext, int t)
{
    extern __shared__ float sm[];
    const uint32_t sbF = s2u(sm);
    const int tid = threadIdx.x, lane = tid & 31, wid = tid >> 5;
    const int warpM = wid & 1, warpN = wid >> 1;       // 2 x 4 warp grid
    const int m_blk = blockIdx.x, nt = blockIdx.y;
    const int q = lane >> 2, kc0 = lane & 3;

    float Cm[4][3][2][4];   // [mtile][gate][e][frag]
    float C1[4][2][4];      // side GEMM (gi_n)
#pragma unroll
    for (int i = 0; i < 4; i++) {
#pragma unroll
        for (int g = 0; g < 3; g++)
#pragma unroll
            for (int e = 0; e < 2; e++)
#pragma unroll
                for (int f = 0; f < 4; f++) Cm[i][g][e][f] = 0.f;
#pragma unroll
        for (int e = 0; e < 2; e++)
#pragma unroll
            for (int f = 0; f < 4; f++) C1[i][e][f] = 0.f;
    }

    load_chunk(sbF, 0, Acur, m_blk, nt, 0, tid);

    for (int c = 0; c < 20; c++) {
        int d = c & 1;
        if (c + 1 < 20) { load_chunk(sbF, (c + 1) & 1, Acur, m_blk, nt, (c + 1) * 32, tid); CPA_WAIT1(); }
        else            { CPA_WAIT0(); }
        __syncthreads();

        const float* A  = sm + S_A(d);
        const float* W  = sm + S_W(d);
        const float* WN = sm + S_WN(d);
        bool side = (c >= 16);
#pragma unroll
        for (int kk = 0; kk < 4; kk++) {
            int kc = kk * 8 + kc0;
            uint32_t a[4][4];
#pragma unroll
            for (int i = 0; i < 4; i++) {
                int m0 = warpM * 64 + i * 16 + q;
                a[i][0] = __float_as_uint(A[m0 * 36 + kc]);
                a[i][1] = __float_as_uint(A[(m0 + 8) * 36 + kc]);
                a[i][2] = __float_as_uint(A[m0 * 36 + kc + 4]);
                a[i][3] = __float_as_uint(A[(m0 + 8) * 36 + kc + 4]);
            }
#pragma unroll
            for (int g = 0; g < 3; g++)
#pragma unroll
                for (int e = 0; e < 2; e++) {
                    int n0 = g * 64 + warpN * 16 + e * 8 + q;
                    uint32_t b0 = __float_as_uint(W[n0 * 36 + kc]);
                    uint32_t b1 = __float_as_uint(W[n0 * 36 + kc + 4]);
#pragma unroll
                    for (int i = 0; i < 4; i++)
                        mma8(Cm[i][g][e], a[i][0], a[i][1], a[i][2], a[i][3], b0, b1);
                }
            if (side) {
#pragma unroll
                for (int e = 0; e < 2; e++) {
                    int n0 = warpN * 16 + e * 8 + q;
                    uint32_t b0 = __float_as_uint(WN[n0 * 36 + kc]);
                    uint32_t b1 = __float_as_uint(WN[n0 * 36 + kc + 4]);
#pragma unroll
                    for (int i = 0; i < 4; i++)
                        mma8(C1[i][e], a[i][0], a[i][1], a[i][2], a[i][3], b0, b1);
                }
            }
        }
        __syncthreads();
    }

    // ---- epilogue: gates + h writes (decay_{t+1} pre-applied) ----
    float bR[4], bZ[4], bNi[4], bNh[4], wdv[4], bdv[4];
#pragma unroll
    for (int e = 0; e < 2; e++)
#pragma unroll
        for (int pos = 0; pos < 2; pos++) {
            int bi = e * 2 + pos;
            int j = nt * 64 + warpN * 16 + e * 8 + 2 * kc0 + pos;
            bR[bi]  = b_ih[j] + b_hh[j];
            bZ[bi]  = b_ih[512 + j] + b_hh[512 + j];
            bNi[bi] = b_ih[1024 + j];
            bNh[bi] = b_hh[1024 + j];
            wdv[bi] = Wd[j];
            bdv[bi] = bdp[j];
        }

#pragma unroll
    for (int i = 0; i < 4; i++) {
#pragma unroll
        for (int hh = 0; hh < 2; hh++) {
            int b = m_blk * 128 + warpM * 64 + i * 16 + q + hh * 8;
            float dtn = (t < 511) ? g_dt[(size_t)(t + 1) * 2048 + b] : 0.0f;
            const float* fr = Fcur + (size_t)b * 512 + nt * 64;
            float* fw = Fnext + (size_t)b * 512 + nt * 64;
            float* aw = Anext + (size_t)b * 640 + nt * 64;
#pragma unroll
            for (int e = 0; e < 2; e++)
#pragma unroll
                for (int pos = 0; pos < 2; pos++) {
                    int bi = e * 2 + pos;
                    int fi = hh * 2 + pos;
                    int jl = warpN * 16 + e * 8 + 2 * kc0 + pos;
                    float sr  = Cm[i][0][e][fi];
                    float sz  = Cm[i][1][e][fi];
                    float sn  = Cm[i][2][e][fi];
                    float gin = C1[i][e][fi];
                    float r = sigmoidf_(sr + bR[bi]);
                    float z = sigmoidf_(sz + bZ[bi]);
                    float nn = tanhfast(gin + bNi[bi] + r * ((sn - gin) + bNh[bi]));
                    float hp = fr[jl];
                    float h = fmaf(-z, nn, nn) + z * hp;
                    if (t < 511)  // exp(-softplus(x)) == sigmoid(-x)
                        h *= sigmoidf_(-(dtn * wdv[bi] + bdv[bi]));
                    fw[jl] = h;
                    aw[jl] = tf32r(h);
                }
        }
    }

    // ---- nt==0 CTAs stage inp_{t+1} into A_next ----
    if (nt == 0 && t < 511) {
#pragma unroll
        for (int i = 0; i < 16; i++) {
            int op = tid + i * 256;          // 4096 float4 ops
            int bl = op >> 5, seg = op & 31;
            int b = m_blk * 128 + bl;
            float4 v;
            if (seg < 16)
                v = ((const float4*)(vals  + (size_t)b * 32768 + (size_t)(t + 1) * 64))[seg];
            else
                v = ((const float4*)(maskp + (size_t)b * 32768 + (size_t)(t + 1) * 64))[seg - 16];
            ((float4*)(Anext + (size_t)b * 640 + 512))[seg] =
                make_float4(tf32r(v.x), tf32r(v.y), tf32r(v.z), tf32r(v.w));
        }
    }
}

// ---------------- head ----------------
__global__ void cru_head_kernel(const float* __restrict__ W_head,
                                const float* __restrict__ b_head,
                                float* __restrict__ out)
{
    __shared__ float sW[8 * 512];
    int tid = threadIdx.x;
    for (int i = tid; i < 4096; i += 128) sW[i] = W_head[i];
    __syncthreads();
    int b = blockIdx.x * 128 + tid;
    const float4* h4 = (const float4*)(g_F0 + (size_t)b * 512);  // final h (t=511 -> F0)
    float acc[8];
#pragma unroll
    for (int n = 0; n < 8; n++) acc[n] = 0.f;
    for (int j4 = 0; j4 < 128; ++j4) {
        float4 v = h4[j4];
#pragma unroll
        for (int n = 0; n < 8; n++) {
            acc[n] = fmaf(v.x, sW[n * 512 + 4 * j4],     acc[n]);
            acc[n] = fmaf(v.y, sW[n * 512 + 4 * j4 + 1], acc[n]);
            acc[n] = fmaf(v.z, sW[n * 512 + 4 * j4 + 2], acc[n]);
            acc[n] = fmaf(v.w, sW[n * 512 + 4 * j4 + 3], acc[n]);
        }
    }
#pragma unroll
    for (int n = 0; n < 8; n++) out[b * 8 + n] = acc[n] + b_head[n];
}

// ---------------- host ----------------
extern "C" void kernel_launch(void* const* d_in, const int* in_sizes, int n_in,
                              void* d_out, int out_size)
{
    const float* vals   = (const float*)d_in[0];
    const float* maskp  = (const float*)d_in[1];
    const float* ts     = (const float*)d_in[2];
    const float* W_ih   = (const float*)d_in[3];
    const float* W_hh   = (const float*)d_in[4];
    const float* b_ih   = (const float*)d_in[5];
    const float* b_hh   = (const float*)d_in[6];
    const float* W_dec  = (const float*)d_in[7];
    const float* b_dec  = (const float*)d_in[8];
    const float* W_head = (const float*)d_in[9];
    const float* b_head = (const float*)d_in[10];
    float* out = (float*)d_out;

    void *pA0, *pA1, *pF0, *pF1;
    cudaGetSymbolAddress(&pA0, g_A0);
    cudaGetSymbolAddress(&pA1, g_A1);
    cudaGetSymbolAddress(&pF0, g_F0);
    cudaGetSymbolAddress(&pF1, g_F1);

    cudaFuncSetAttribute(cru_step_kernel,
                         cudaFuncAttributeMaxDynamicSharedMemorySize, SMEM_BYTES);

    prep_w_kernel<<<3840, 256>>>(W_ih, W_hh);
    prep_wn_kernel<<<256, 256>>>(W_ih);
    prep_dt_kernel<<<512, 256>>>(ts);
    prep_a0_kernel<<<2048, 256>>>(vals, maskp);

    dim3 grid(16, 8);
    for (int t = 0; t < 512; ++t) {
        const float* Acur = (t & 1) ? (const float*)pA1 : (const float*)pA0;
        float*       Anxt = (t & 1) ? (float*)pA0 : (float*)pA1;
        const float* Fcur = (t & 1) ? (const float*)pF1 : (const float*)pF0;
        float*       Fnxt = (t & 1) ? (float*)pF0 : (float*)pF1;
        cru_step_kernel<<<grid, 256, SMEM_BYTES>>>(
            vals, maskp, b_ih, b_hh, W_dec, b_dec, Acur, Anxt, Fcur, Fnxt, t);
    }

    cru_head_kernel<<<16, 128>>>(W_head, b_head, out);
}

// round 14
// speedup vs baseline: 4.9838x; 1.6499x over previous
#include <cuda_runtime.h>
#include <cuda_fp16.h>
#include <cstdint>
#include <math.h>

// CRU: B=2048, T=512, D=64, H=512, NT=8
// Recurrence on tensor pipe via mma.sync.m16n8k16.f16 (fp32 accumulate).
// fp16 mantissa == tf32 mantissa (10 bits) -> same accuracy class, but
// HALF the HMMA instructions (K=16/instr), half the smem/LDS traffic,
// half the chunk count vs the round-11 tf32 kernel.
//
// Per step t (one launch, grid (16 m, 8 nt), 256 threads):
//   A (ping-pong, fp16) = [ h (512) | inp_t (128) ]  row-major [2048][640]
//   gW fp16 [1536][640]: per nt-tile gate-blocked rows nt*192 + g*64 + jl
//   gWn fp16 [512][128]: W_ih n-gate rows (side GEMM splits gi_n / gh_n)
//   gF (ping-pong, fp32) = exact h for the z*h_prev blend + head GEMM.
//   Epilogue: fused gates; h_next stored with decay_{t+1} pre-applied.
//
// THIRD submission of this exact source. R12/R13 died to container-level
// failures ("GB300 container failed twice" = broker error, not harness
// output). Audit: no spin loops (all waits are bounded cp.async.wait_group
// with matching commits), no arch-specific PTX (baseline sm_80 mma.sync),
// all addresses alignment-checked and in-bounds; the structurally identical
// tf32 variant passed in R11. Decision rule: pass => infra window confirmed;
// fail => source-correlated, revert to R11 lineage.

__device__ __half g_A0[2048 * 640];
__device__ __half g_A1[2048 * 640];
__device__ float  g_F0[2048 * 512];
__device__ float  g_F1[2048 * 512];
__device__ __half g_W [1536 * 640];
__device__ __half g_Wn[ 512 * 128];
__device__ float  g_dt[ 512 * 2048];

// smem layout in HALF units; row stride 72 halves (36 half2 -> conflict-free)
#define S_A(d)   ((d) * 9216)                  // [128][72] x2
#define S_W(d)   (18432 + (d) * 13824)         // [192][72] x2
#define S_WN(d)  (46080 + (d) * 4608)          // [64][72]  x2
#define SMEM_HALFS 55296
#define SMEM_BYTES (SMEM_HALFS * 2)            // 110592

__device__ __forceinline__ uint32_t s2u(const void* p) {
    uint32_t a;
    asm("{ .reg .u64 t; cvta.to.shared.u64 t, %1; cvt.u32.u64 %0, t; }" : "=r"(a) : "l"(p));
    return a;
}
__device__ __forceinline__ void cpa16(uint32_t dst, const void* src) {
    asm volatile("cp.async.cg.shared.global [%0], [%1], 16;" :: "r"(dst), "l"(src));
}
#define CPA_COMMIT() asm volatile("cp.async.commit_group;" ::: "memory")
#define CPA_WAIT1()  asm volatile("cp.async.wait_group 1;" ::: "memory")
#define CPA_WAIT0()  asm volatile("cp.async.wait_group 0;" ::: "memory")

__device__ __forceinline__ void mma16(float* c, uint32_t a0, uint32_t a1,
                                      uint32_t a2, uint32_t a3,
                                      uint32_t b0, uint32_t b1) {
    asm volatile("mma.sync.aligned.m16n8k16.row.col.f32.f16.f16.f32 "
        "{%0,%1,%2,%3}, {%4,%5,%6,%7}, {%8,%9}, {%0,%1,%2,%3};"
        : "+f"(c[0]), "+f"(c[1]), "+f"(c[2]), "+f"(c[3])
        : "r"(a0), "r"(a1), "r"(a2), "r"(a3), "r"(b0), "r"(b1));
}

__device__ __forceinline__ float sigmoidf_(float x) { return 1.0f / (1.0f + __expf(-x)); }
__device__ __forceinline__ float tanhfast(float x) {
    float y; asm("tanh.approx.f32 %0, %1;" : "=f"(y) : "f"(x)); return y;
}

// ---------------- prep kernels ----------------
__global__ void prep_w_kernel(const float* __restrict__ W_ih, const float* __restrict__ W_hh) {
    int idx = blockIdx.x * 256 + threadIdx.x;          // 1536*640
    if (idx >= 1536 * 640) return;
    int r = idx / 640, k = idx - r * 640;
    int nt = r / 192, rem = r - nt * 192;
    int g = rem / 64, jl = rem - g * 64;
    int row = g * 512 + nt * 64 + jl;
    float w = (k < 512) ? W_hh[(size_t)row * 512 + k] : W_ih[(size_t)row * 128 + (k - 512)];
    g_W[idx] = __float2half_rn(w);
}
__global__ void prep_wn_kernel(const float* __restrict__ W_ih) {
    int idx = blockIdx.x * 256 + threadIdx.x;          // 512*128
    int j = idx >> 7, k = idx & 127;
    g_Wn[idx] = __float2half_rn(W_ih[(size_t)(1024 + j) * 128 + k]);
}
__global__ void prep_dt_kernel(const float* __restrict__ ts) {
    int t = blockIdx.x;
    for (int b = threadIdx.x; b < 2048; b += 256) {
        float d = 0.0f;
        if (t > 0) d = ts[(size_t)b * 512 + t] - ts[(size_t)b * 512 + t - 1];
        g_dt[t * 2048 + b] = d;
    }
}
__global__ void prep_a0_kernel(const float* __restrict__ vals, const float* __restrict__ maskp) {
    int b = blockIdx.x;
    for (int i = threadIdx.x; i < 640; i += 256) {
        float v = 0.0f;
        if (i >= 512 && i < 576)      v = vals [(size_t)b * 32768 + (i - 512)];
        else if (i >= 576)            v = maskp[(size_t)b * 32768 + (i - 576)];
        g_A0[(size_t)b * 640 + i] = __float2half_rn(v);
    }
    for (int i = threadIdx.x; i < 512; i += 256)
        g_F0[(size_t)b * 512 + i] = 0.0f;
}

// ---------------- step kernel ----------------
// chunk = K=64 halves. A: 128x64 (8 segs/row), W: 192x64, WN: 64x64 (only k>=512 chunks)
__device__ __forceinline__ void load_chunk(uint32_t sbH, int d,
    const __half* __restrict__ Acur, int m_blk, int nt, int kbase, int tid)
{
#pragma unroll
    for (int i = 0; i < 4; i++) {                       // A: 128 rows x 8 segs
        int op = tid + i * 256;
        int m = op >> 3, seg = op & 7;
        uint32_t dst = sbH + (uint32_t)(S_A(d) + m * 72 + seg * 8) * 2u;
        cpa16(dst, Acur + (size_t)(m_blk * 128 + m) * 640 + kbase + seg * 8);
    }
#pragma unroll
    for (int i = 0; i < 6; i++) {                       // W: 192 rows x 8 segs
        int op = tid + i * 256;
        int n = op >> 3, seg = op & 7;
        uint32_t dst = sbH + (uint32_t)(S_W(d) + n * 72 + seg * 8) * 2u;
        cpa16(dst, g_W + (size_t)(nt * 192 + n) * 640 + kbase + seg * 8);
    }
    if (kbase >= 512) {
#pragma unroll
        for (int i = 0; i < 2; i++) {                   // Wn: 64 rows x 8 segs
            int op = tid + i * 256;
            int n = op >> 3, seg = op & 7;
            uint32_t dst = sbH + (uint32_t)(S_WN(d) + n * 72 + seg * 8) * 2u;
            cpa16(dst, g_Wn + (size_t)(nt * 64 + n) * 128 + (kbase - 512) + seg * 8);
        }
    }
    CPA_COMMIT();
}

__global__ void __launch_bounds__(256, 1) cru_step_kernel(
    const float* __restrict__ vals, const float* __restrict__ maskp,
    const float* __restrict__ b_ih, const float* __restrict__ b_hh,
    const float* __restrict__ Wd,  const float* __restrict__ bdp,
    const __half* __restrict__ Acur, __half* __restrict__ Anext,
    const float* __restrict__ Fcur, float* __restrict__ Fnext, int t)
{
    extern __shared__ __half smh[];
    const uint32_t sbH = s2u(smh);
    const int tid = threadIdx.x, lane = tid & 31, wid = tid >> 5;
    const int warpM = wid & 1, warpN = wid >> 1;       // 2 x 4 warp grid
    const int m_blk = blockIdx.x, nt = blockIdx.y;
    const int q = lane >> 2, kc0 = lane & 3;

    float Cm[4][3][2][4];   // [mtile][gate][e][frag]
    float C1[4][2][4];      // side GEMM (gi_n)
#pragma unroll
    for (int i = 0; i < 4; i++) {
#pragma unroll
        for (int g = 0; g < 3; g++)
#pragma unroll
            for (int e = 0; e < 2; e++)
#pragma unroll
                for (int f = 0; f < 4; f++) Cm[i][g][e][f] = 0.f;
#pragma unroll
        for (int e = 0; e < 2; e++)
#pragma unroll
            for (int f = 0; f < 4; f++) C1[i][e][f] = 0.f;
    }

    load_chunk(sbH, 0, Acur, m_blk, nt, 0, tid);

    for (int c = 0; c < 10; c++) {
        int d = c & 1;
        if (c + 1 < 10) { load_chunk(sbH, (c + 1) & 1, Acur, m_blk, nt, (c + 1) * 64, tid); CPA_WAIT1(); }
        else            { CPA_WAIT0(); }
        __syncthreads();

        // all smem indexing in half2 (u32) units; row stride = 36
        const uint32_t* A2  = (const uint32_t*)(smh + S_A(d));
        const uint32_t* W2  = (const uint32_t*)(smh + S_W(d));
        const uint32_t* WN2 = (const uint32_t*)(smh + S_WN(d));
        bool side = (c >= 8);
#pragma unroll
        for (int kk = 0; kk < 4; kk++) {               // K=16 per kk
            int kc = kk * 8 + kc0;
            uint32_t a[4][4];
#pragma unroll
            for (int i = 0; i < 4; i++) {
                int m0 = warpM * 64 + i * 16 + q;
                a[i][0] = A2[m0 * 36 + kc];
                a[i][1] = A2[(m0 + 8) * 36 + kc];
                a[i][2] = A2[m0 * 36 + kc + 4];
                a[i][3] = A2[(m0 + 8) * 36 + kc + 4];
            }
#pragma unroll
            for (int g = 0; g < 3; g++)
#pragma unroll
                for (int e = 0; e < 2; e++) {
                    int n0 = (g * 64 + warpN * 16 + e * 8 + q) * 36;
                    uint32_t b0 = W2[n0 + kc];
                    uint32_t b1 = W2[n0 + kc + 4];
#pragma unroll
                    for (int i = 0; i < 4; i++)
                        mma16(Cm[i][g][e], a[i][0], a[i][1], a[i][2], a[i][3], b0, b1);
                }
            if (side) {
#pragma unroll
                for (int e = 0; e < 2; e++) {
                    int n0 = (warpN * 16 + e * 8 + q) * 36;
                    uint32_t b0 = WN2[n0 + kc];
                    uint32_t b1 = WN2[n0 + kc + 4];
#pragma unroll
                    for (int i = 0; i < 4; i++)
                        mma16(C1[i][e], a[i][0], a[i][1], a[i][2], a[i][3], b0, b1);
                }
            }
        }
        __syncthreads();
    }

    // ---- epilogue: gates + h writes (decay_{t+1} pre-applied) ----
    float bR[4], bZ[4], bNi[4], bNh[4], wdv[4], bdv[4];
#pragma unroll
    for (int e = 0; e < 2; e++)
#pragma unroll
        for (int pos = 0; pos < 2; pos++) {
            int bi = e * 2 + pos;
            int j = nt * 64 + warpN * 16 + e * 8 + 2 * kc0 + pos;
            bR[bi]  = b_ih[j] + b_hh[j];
            bZ[bi]  = b_ih[512 + j] + b_hh[512 + j];
            bNi[bi] = b_ih[1024 + j];
            bNh[bi] = b_hh[1024 + j];
            wdv[bi] = Wd[j];
            bdv[bi] = bdp[j];
        }

#pragma unroll
    for (int i = 0; i < 4; i++) {
#pragma unroll
        for (int hh = 0; hh < 2; hh++) {
            int b = m_blk * 128 + warpM * 64 + i * 16 + q + hh * 8;
            float dtn = (t < 511) ? g_dt[(size_t)(t + 1) * 2048 + b] : 0.0f;
            const float* fr = Fcur + (size_t)b * 512 + nt * 64;
            float* fw = Fnext + (size_t)b * 512 + nt * 64;
            __half* aw = Anext + (size_t)b * 640 + nt * 64;
#pragma unroll
            for (int e = 0; e < 2; e++) {
                float hv[2];
#pragma unroll
                for (int pos = 0; pos < 2; pos++) {
                    int bi = e * 2 + pos;
                    int fi = hh * 2 + pos;
                    int jl = warpN * 16 + e * 8 + 2 * kc0 + pos;
                    float sr  = Cm[i][0][e][fi];
                    float sz  = Cm[i][1][e][fi];
                    float sn  = Cm[i][2][e][fi];
                    float gin = C1[i][e][fi];
                    float r = sigmoidf_(sr + bR[bi]);
                    float z = sigmoidf_(sz + bZ[bi]);
                    float nn = tanhfast(gin + bNi[bi] + r * ((sn - gin) + bNh[bi]));
                    float hp = fr[jl];
                    float h = fmaf(-z, nn, nn) + z * hp;
                    if (t < 511)  // exp(-softplus(x)) == sigmoid(-x)
                        h *= sigmoidf_(-(dtn * wdv[bi] + bdv[bi]));
                    hv[pos] = h;
                }
                int jlb = warpN * 16 + e * 8 + 2 * kc0;
                *(float2*)(fw + jlb) = make_float2(hv[0], hv[1]);
                *(__half2*)(aw + jlb) = __floats2half2_rn(hv[0], hv[1]);
            }
        }
    }

    // ---- nt==0 CTAs stage inp_{t+1} (fp16) into A_next ----
    if (nt == 0 && t < 511) {
#pragma unroll
        for (int i = 0; i < 16; i++) {
            int op = tid + i * 256;          // 4096 float4-load ops
            int bl = op >> 5, seg = op & 31;
            int b = m_blk * 128 + bl;
            float4 v;
            if (seg < 16)
                v = ((const float4*)(vals  + (size_t)b * 32768 + (size_t)(t + 1) * 64))[seg];
            else
                v = ((const float4*)(maskp + (size_t)b * 32768 + (size_t)(t + 1) * 64))[seg - 16];
            __half2 h0 = __floats2half2_rn(v.x, v.y);
            __half2 h1 = __floats2half2_rn(v.z, v.w);
            __half2* dst = (__half2*)(Anext + (size_t)b * 640 + 512 + seg * 4);
            dst[0] = h0; dst[1] = h1;
        }
    }
}

// ---------------- head ----------------
__global__ void cru_head_kernel(const float* __restrict__ W_head,
                                const float* __restrict__ b_head,
                                float* __restrict__ out)
{
    __shared__ float sW[8 * 512];
    int tid = threadIdx.x;
    for (int i = tid; i < 4096; i += 128) sW[i] = W_head[i];
    __syncthreads();
    int b = blockIdx.x * 128 + tid;
    const float4* h4 = (const float4*)(g_F0 + (size_t)b * 512);  // final h (t=511 -> F0)
    float acc[8];
#pragma unroll
    for (int n = 0; n < 8; n++) acc[n] = 0.f;
    for (int j4 = 0; j4 < 128; ++j4) {
        float4 v = h4[j4];
#pragma unroll
        for (int n = 0; n < 8; n++) {
            acc[n] = fmaf(v.x, sW[n * 512 + 4 * j4],     acc[n]);
            acc[n] = fmaf(v.y, sW[n * 512 + 4 * j4 + 1], acc[n]);
            acc[n] = fmaf(v.z, sW[n * 512 + 4 * j4 + 2], acc[n]);
            acc[n] = fmaf(v.w, sW[n * 512 + 4 * j4 + 3], acc[n]);
        }
    }
#pragma unroll
    for (int n = 0; n < 8; n++) out[b * 8 + n] = acc[n] + b_head[n];
}

// ---------------- host ----------------
extern "C" void kernel_launch(void* const* d_in, const int* in_sizes, int n_in,
                              void* d_out, int out_size)
{
    const float* vals   = (const float*)d_in[0];
    const float* maskp  = (const float*)d_in[1];
    const float* ts     = (const float*)d_in[2];
    const float* W_ih   = (const float*)d_in[3];
    const float* W_hh   = (const float*)d_in[4];
    const float* b_ih   = (const float*)d_in[5];
    const float* b_hh   = (const float*)d_in[6];
    const float* W_dec  = (const float*)d_in[7];
    const float* b_dec  = (const float*)d_in[8];
    const float* W_head = (const float*)d_in[9];
    const float* b_head = (const float*)d_in[10];
    float* out = (float*)d_out;

    void *pA0, *pA1, *pF0, *pF1;
    cudaGetSymbolAddress(&pA0, g_A0);
    cudaGetSymbolAddress(&pA1, g_A1);
    cudaGetSymbolAddress(&pF0, g_F0);
    cudaGetSymbolAddress(&pF1, g_F1);

    cudaFuncSetAttribute(cru_step_kernel,
                         cudaFuncAttributeMaxDynamicSharedMemorySize, SMEM_BYTES);

    prep_w_kernel<<<3840, 256>>>(W_ih, W_hh);
    prep_wn_kernel<<<256, 256>>>(W_ih);
    prep_dt_kernel<<<512, 256>>>(ts);
    prep_a0_kernel<<<2048, 256>>>(vals, maskp);

    dim3 grid(16, 8);
    for (int t = 0; t < 512; ++t) {
        const __half* Acur = (t & 1) ? (const __half*)pA1 : (const __half*)pA0;
        __half*       Anxt = (t & 1) ? (__half*)pA0 : (__half*)pA1;
        const float*  Fcur = (t & 1) ? (const float*)pF1 : (const float*)pF0;
        float*        Fnxt = (t & 1) ? (float*)pF0 : (float*)pF1;
        cru_step_kernel<<<grid, 256, SMEM_BYTES>>>(
            vals, maskp, b_ih, b_hh, W_dec, b_dec, Acur, Anxt, Fcur, Fnxt, t);
    }

    cru_head_kernel<<<16, 128>>>(W_head, b_head, out);
}